// round 11
// baseline (speedup 1.0000x reference)
#include <cuda_runtime.h>
#include <cuda_bf16.h>
#include <math.h>
#include <stdint.h>

// ============================================================================
// SoftVectorQuantizer via mma.sync fp16 (m16n8k16, fp32 accum), flash-style.
// z[8,64,64,64] f32, embedding[4096,64] f32.
// out = concat(z_q[2097152], entropy(=0), indices[32768] as f32)
//
// e-split build: CTA = 64 rows, 4 warps = 2 row-groups x 2 e-halves.
// Each warp: M=32 rows x E=32 embeddings -> B-frag bytes per MMA HALVED
// (the smem crossbar was the structural co-binder). O is additive over e
// (fixed-shift softmax), so e-halves sum O via smem once at the end.
// Grid 512, 3 CTAs/SM (12 warps), 2x per-warp ILP from dual m16 streams.
// fp32 ex2. argmax: union of per-half fp16 top-2 (4 cands) + exact refine.
// ============================================================================

#define N_E     4096
#define D       64
#define HW      4096
#define NZ      2097152
#define NROWS   32768
#define CTAS    512          // 64 rows per CTA
#define THREADS 128          // 4 warps: 2 row-groups x 2 e-halves
#define NT      64           // embedding tiles of 64
#define CE      20.60992529f // log2(e)/0.07

__device__ float    g_embn[N_E * D];      // normalized embedding (refine)
__device__ uint32_t g_kf[NT * 2048];      // fp16 K B-frags (uint4-grouped), 8KB/tile
__device__ uint16_t g_vf[NT * 4096];      // fp16 V B-frags (uint4-grouped), 8KB/tile

__device__ __forceinline__ float ex2f(float x) {
    float r; asm("ex2.approx.f32 %0, %1;" : "=f"(r) : "f"(x)); return r;
}
__device__ __forceinline__ uint32_t pack_h2(float lo, float hi) {
    uint32_t r; asm("cvt.rn.f16x2.f32 %0, %1, %2;" : "=r"(r) : "f"(hi), "f"(lo));
    return r;
}
__device__ __forceinline__ uint32_t smem_u32(const void* p) {
    uint32_t a;
    asm("{ .reg .u64 t; cvta.to.shared.u64 t, %1; cvt.u32.u64 %0, t; }"
        : "=r"(a) : "l"(p));
    return a;
}
__device__ __forceinline__ void cpa16(uint32_t dst, const void* src) {
    asm volatile("cp.async.cg.shared.global [%0], [%1], 16;" :: "r"(dst), "l"(src));
}
__device__ __forceinline__ void mma_f16(float c[4], const uint32_t a[4],
                                        uint32_t b0, uint32_t b1) {
    asm volatile(
        "mma.sync.aligned.m16n8k16.row.col.f32.f16.f16.f32 "
        "{%0,%1,%2,%3},{%4,%5,%6,%7},{%8,%9},{%0,%1,%2,%3};"
        : "+f"(c[0]), "+f"(c[1]), "+f"(c[2]), "+f"(c[3])
        : "r"(a[0]), "r"(a[1]), "r"(a[2]), "r"(a[3]), "r"(b0), "r"(b1));
}

// Fragment half-index helpers (uint4-grouped layouts, 4096 halves per tile).
// GEMM1 (S = Q.K^T): n-dim = e, k-dim = d.
__device__ __forceinline__ int kf_hidx(int e, int d) {
    return ((((e >> 3) * 2 + (d >> 5)) * 32 + (e & 7) * 4 + ((d >> 1) & 3)) * 8)
           + ((d >> 4) & 1) * 4 + ((d >> 3) & 1) * 2 + (d & 1);
}
// GEMM2 (O += P.V): n-dim = d, k-dim = e.
__device__ __forceinline__ int vf_hidx(int e, int d) {
    return ((((d >> 4) * 4 + (e >> 4)) * 32 + (d & 7) * 4 + ((e >> 1) & 3)) * 8)
           + ((d >> 3) & 1) * 4 + ((e >> 3) & 1) * 2 + (e & 1);
}

// ---------------------------------------------------------------------------
// prep: normalize embedding rows + scatter fp16 B-fragments (once)
// ---------------------------------------------------------------------------
__global__ void prep_kernel(const float* __restrict__ emb) {
    int e = blockIdx.x * 4 + (threadIdx.x >> 5);
    int lane = threadIdx.x & 31;
    float2 v = reinterpret_cast<const float2*>(emb + (size_t)e * D)[lane];
    float s = v.x * v.x + v.y * v.y;
    #pragma unroll
    for (int o = 16; o; o >>= 1) s += __shfl_xor_sync(0xffffffffu, s, o);
    float inv = 1.0f / fmaxf(sqrtf(s), 1e-12f);
    float2 r; r.x = v.x * inv; r.y = v.y * inv;
    reinterpret_cast<float2*>(g_embn + (size_t)e * D)[lane] = r;

    int tile = e >> 6, el = e & 63;
    int d0 = 2 * lane, d1 = 2 * lane + 1;
    __half h0 = __float2half_rn(r.x), h1 = __float2half_rn(r.y);
    uint16_t u0 = *reinterpret_cast<uint16_t*>(&h0);
    uint16_t u1 = *reinterpret_cast<uint16_t*>(&h1);
    g_kf[tile * 2048 + (kf_hidx(el, d0) >> 1)] = (uint32_t)u0 | ((uint32_t)u1 << 16);
    g_vf[tile * 4096 + vf_hidx(el, d0)] = u0;
    g_vf[tile * 4096 + vf_hidx(el, d1)] = u1;
}

// ---------------------------------------------------------------------------
// main fused kernel
// ---------------------------------------------------------------------------
__global__ void __launch_bounds__(THREADS, 3)
svq_main_kernel(const float* __restrict__ z, float* __restrict__ out) {
    __shared__ uint4 s_kf[3][512];   // 24 KB (triple-buffered K tiles)
    __shared__ uint4 s_vf[3][512];   // 24 KB (triple-buffered V tiles)
    // reused after mainloop: s_kf region -> float O-scratch, s_vf -> cand ints

    const int tid  = threadIdx.x;
    const int w    = tid >> 5;
    const int lane = tid & 31;
    const int q    = lane & 3;
    const int r    = lane >> 2;
    const int rg   = w >> 1;         // row group (0/1)
    const int eh   = w & 1;          // embedding half (0/1)
    const int wrow = rg * 32;        // warp's first row (CTA-local)
    const unsigned FULL = 0xffffffffu;

    const uint32_t kf_s[3] = {smem_u32(&s_kf[0][0]), smem_u32(&s_kf[1][0]),
                              smem_u32(&s_kf[2][0])};
    const uint32_t vf_s[3] = {smem_u32(&s_vf[0][0]), smem_u32(&s_vf[1][0]),
                              smem_u32(&s_vf[2][0])};

    // ---- kick off async copies of tiles 0 and 1 (8KB K + 8KB V each) ----
    #pragma unroll
    for (int tb = 0; tb < 2; tb++) {
        const char* gk = (const char*)g_kf + (size_t)tb * 8192;
        const char* gv = (const char*)g_vf + (size_t)tb * 8192;
        #pragma unroll
        for (int i = 0; i < 4; i++) {
            cpa16(kf_s[tb] + (i * 128 + tid) * 16, gk + (i * 128 + tid) * 16);
            cpa16(vf_s[tb] + (i * 128 + tid) * 16, gv + (i * 128 + tid) * 16);
        }
        asm volatile("cp.async.commit_group;");
    }

    // ---- Q: 32 rows/warp (2 x m16), l2-normalize, fp16 A-frags ----
    const int n0  = blockIdx.x * 64;
    const int bb  = n0 >> 12;
    const int hw0 = n0 & (HW - 1);
    const float* zbase = z + (size_t)bb * D * HW + hw0;

    uint32_t qa[2][4][4];
    {
        float ssq[4] = {0.f, 0.f, 0.f, 0.f};
        float zq[2][4][4][2];
        #pragma unroll
        for (int mi = 0; mi < 2; mi++)
            #pragma unroll
            for (int ks = 0; ks < 4; ks++)
                #pragma unroll
                for (int a = 0; a < 4; a++) {
                    int row = wrow + mi * 16 + r + (a & 1) * 8;
                    int k   = ks * 16 + 2 * q + ((a & 2) ? 8 : 0);
                    float v0 = zbase[(size_t)k * HW + row];
                    float v1 = zbase[(size_t)(k + 1) * HW + row];
                    zq[mi][ks][a][0] = v0;
                    zq[mi][ks][a][1] = v1;
                    ssq[mi * 2 + (a & 1)] += v0 * v0 + v1 * v1;
                }
        #pragma unroll
        for (int s = 0; s < 4; s++) {
            ssq[s] += __shfl_xor_sync(FULL, ssq[s], 1);
            ssq[s] += __shfl_xor_sync(FULL, ssq[s], 2);
            ssq[s] = 1.0f / fmaxf(sqrtf(ssq[s]), 1e-12f);
        }
        #pragma unroll
        for (int mi = 0; mi < 2; mi++)
            #pragma unroll
            for (int ks = 0; ks < 4; ks++)
                #pragma unroll
                for (int a = 0; a < 4; a++) {
                    float sc = ssq[mi * 2 + (a & 1)];
                    qa[mi][ks][a] =
                        pack_h2(zq[mi][ks][a][0] * sc, zq[mi][ks][a][1] * sc);
                }
    }

    float o[2][8][4];
    #pragma unroll
    for (int mi = 0; mi < 2; mi++)
        #pragma unroll
        for (int di = 0; di < 8; di++)
            #pragma unroll
            for (int c = 0; c < 4; c++) o[mi][di][c] = 0.f;
    float m1[4] = {-1e30f, -1e30f, -1e30f, -1e30f};
    float m2[4] = {-1e30f, -1e30f, -1e30f, -1e30f};
    int   i1[4] = {0, 0, 0, 0}, i2[4] = {0, 0, 0, 0};

    for (int t = 0; t < NT; t++) {
        const int cur = t % 3;
        if (t + 1 < NT) asm volatile("cp.async.wait_group 1;");
        else            asm volatile("cp.async.wait_group 0;");
        __syncthreads();   // single barrier per tile (triple buffering)

        if (t + 2 < NT) {
            const int nb = (t + 2) % 3;
            const char* gk = (const char*)g_kf + (size_t)(t + 2) * 8192;
            const char* gv = (const char*)g_vf + (size_t)(t + 2) * 8192;
            #pragma unroll
            for (int i = 0; i < 4; i++) {
                cpa16(kf_s[nb] + (i * 128 + tid) * 16, gk + (i * 128 + tid) * 16);
                cpa16(vf_s[nb] + (i * 128 + tid) * 16, gv + (i * 128 + tid) * 16);
            }
            asm volatile("cp.async.commit_group;");
        }

        const uint4* ks4 = s_kf[cur];
        const uint4* vs4 = s_vf[cur];

        #pragma unroll
        for (int pi = 0; pi < 2; pi++) {           // 16-e chunks of this half
            const int pg = eh * 2 + pi;            // global 16-e chunk

            // GEMM1: 16 embeddings (2 n8 chunks), both m16 tiles
            float s[2][2][4];
            #pragma unroll
            for (int nih = 0; nih < 2; nih++) {
                const int ni = eh * 4 + pi * 2 + nih;
                uint4 b0 = ks4[(ni * 2 + 0) * 32 + lane];
                uint4 b1 = ks4[(ni * 2 + 1) * 32 + lane];
                #pragma unroll
                for (int mi = 0; mi < 2; mi++) {
                    #pragma unroll
                    for (int c = 0; c < 4; c++) s[mi][nih][c] = 0.f;
                    mma_f16(s[mi][nih], qa[mi][0], b0.x, b0.y);
                    mma_f16(s[mi][nih], qa[mi][1], b0.z, b0.w);
                    mma_f16(s[mi][nih], qa[mi][2], b1.x, b1.y);
                    mma_f16(s[mi][nih], qa[mi][3], b1.z, b1.w);
                }
            }
            // exp (fp32) -> fp16 A-frags (layout-aligned, no shuffles)
            uint32_t a[2][4];
            #pragma unroll
            for (int mi = 0; mi < 2; mi++)
                #pragma unroll
                for (int nih = 0; nih < 2; nih++) {
                    float p0 = ex2f(fmaf(s[mi][nih][0], CE, -CE));
                    float p1 = ex2f(fmaf(s[mi][nih][1], CE, -CE));
                    float p2 = ex2f(fmaf(s[mi][nih][2], CE, -CE));
                    float p3 = ex2f(fmaf(s[mi][nih][3], CE, -CE));
                    a[mi][nih * 2 + 0] = pack_h2(p0, p1);
                    a[mi][nih * 2 + 1] = pack_h2(p2, p3);
                }
            // GEMM2: O += P(k16 = 16 e of chunk pg) * V
            #pragma unroll
            for (int dp = 0; dp < 4; dp++) {
                uint4 bv = vs4[(dp * 4 + pg) * 32 + lane];
                mma_f16(o[0][2 * dp],     a[0], bv.x, bv.y);
                mma_f16(o[1][2 * dp],     a[1], bv.x, bv.y);
                mma_f16(o[0][2 * dp + 1], a[0], bv.z, bv.w);
                mma_f16(o[1][2 * dp + 1], a[1], bv.z, bv.w);
            }
            // top-2 tracking (per e-half), gated by pair-max
            #pragma unroll
            for (int mi = 0; mi < 2; mi++)
                #pragma unroll
                for (int nih = 0; nih < 2; nih++)
                    #pragma unroll
                    for (int sl = 0; sl < 2; sl++) {
                        int slot = mi * 2 + sl;
                        float s0 = s[mi][nih][sl * 2], s1 = s[mi][nih][sl * 2 + 1];
                        if (fmaxf(s0, s1) > m2[slot]) {
                            int col0 = t * 64 + (eh * 4 + pi * 2 + nih) * 8 + 2 * q;
                            if (s0 > m2[slot]) {
                                if (s0 > m1[slot]) {
                                    m2[slot] = m1[slot]; i2[slot] = i1[slot];
                                    m1[slot] = s0;       i1[slot] = col0;
                                } else { m2[slot] = s0; i2[slot] = col0; }
                            }
                            if (s1 > m2[slot]) {
                                if (s1 > m1[slot]) {
                                    m2[slot] = m1[slot]; i2[slot] = i1[slot];
                                    m1[slot] = s1;       i1[slot] = col0 + 1;
                                } else { m2[slot] = s1; i2[slot] = col0 + 1; }
                            }
                        }
                    }
        }
    }

    // ---- epilogue: combine e-halves, l2norm, store; candidates; refine ----
    __syncthreads();   // all tile reads done -> reuse smem as scratch
    float* sO   = reinterpret_cast<float*>(&s_kf[0][0]);  // [64 rows][65] floats
    int*   cand = reinterpret_cast<int*>(&s_vf[0][0]);    // [64 rows][4]

    if (eh == 1) {
        #pragma unroll
        for (int mi = 0; mi < 2; mi++)
            #pragma unroll
            for (int di = 0; di < 8; di++)
                #pragma unroll
                for (int c = 0; c < 4; c++) {
                    int row = wrow + mi * 16 + r + (c >> 1) * 8;
                    int d   = di * 8 + 2 * q + (c & 1);
                    sO[row * 65 + d] = o[mi][di][c];
                }
    }

    // merge top-2 across the 4 quad lanes of each row, write candidates
    #pragma unroll
    for (int s = 0; s < 4; s++) {
        #pragma unroll
        for (int off = 1; off <= 2; off++) {
            float om1 = __shfl_xor_sync(FULL, m1[s], off);
            int   oi1 = __shfl_xor_sync(FULL, i1[s], off);
            float om2 = __shfl_xor_sync(FULL, m2[s], off);
            int   oi2 = __shfl_xor_sync(FULL, i2[s], off);
            if (om1 > m1[s] || (om1 == m1[s] && oi1 < i1[s])) {
                float tm = m1[s]; int ti = i1[s];
                m1[s] = om1; i1[s] = oi1;
                om1 = tm; oi1 = ti;
            }
            if (om1 > m2[s] || (om1 == m2[s] && oi1 < i2[s])) { m2[s] = om1; i2[s] = oi1; }
            if (om2 > m2[s] || (om2 == m2[s] && oi2 < i2[s])) { m2[s] = om2; i2[s] = oi2; }
        }
    }
    if (q == 0) {
        #pragma unroll
        for (int s = 0; s < 4; s++) {
            int row = wrow + (s >> 1) * 16 + (s & 1) * 8 + r;
            cand[row * 4 + eh * 2 + 0] = i1[s];
            cand[row * 4 + eh * 2 + 1] = i2[s];
        }
    }
    __syncthreads();

    if (eh == 0) {
        // add the partner half's O, l2norm per row, store z_q
        float oss[4] = {0.f, 0.f, 0.f, 0.f};
        #pragma unroll
        for (int mi = 0; mi < 2; mi++)
            #pragma unroll
            for (int di = 0; di < 8; di++)
                #pragma unroll
                for (int c = 0; c < 4; c++) {
                    int row = wrow + mi * 16 + r + (c >> 1) * 8;
                    int d   = di * 8 + 2 * q + (c & 1);
                    float v = o[mi][di][c] + sO[row * 65 + d];
                    o[mi][di][c] = v;
                    oss[mi * 2 + (c >> 1)] += v * v;
                }
        #pragma unroll
        for (int s = 0; s < 4; s++) {
            oss[s] += __shfl_xor_sync(FULL, oss[s], 1);
            oss[s] += __shfl_xor_sync(FULL, oss[s], 2);
            oss[s] = 1.0f / fmaxf(sqrtf(oss[s]), 1e-12f);
        }
        float* ob = out + (size_t)bb * D * HW + hw0;
        #pragma unroll
        for (int mi = 0; mi < 2; mi++)
            #pragma unroll
            for (int di = 0; di < 8; di++) {
                int d0 = di * 8 + 2 * q;
                int rl = wrow + mi * 16 + r, rh = rl + 8;
                ob[(size_t)d0 * HW + rl]       = o[mi][di][0] * oss[mi * 2];
                ob[(size_t)(d0 + 1) * HW + rl] = o[mi][di][1] * oss[mi * 2];
                ob[(size_t)d0 * HW + rh]       = o[mi][di][2] * oss[mi * 2 + 1];
                ob[(size_t)(d0 + 1) * HW + rh] = o[mi][di][3] * oss[mi * 2 + 1];
            }
    }

    // ---- fused exact-fp32 argmax refine: 2 threads/row over 4 candidates ----
    {
        const int row  = tid >> 1;       // CTA-local row 0..63
        const int half = tid & 1;        // channel half
        int cs[4];
        #pragma unroll
        for (int k = 0; k < 4; k++) cs[k] = cand[row * 4 + k];
        const float* zb = zbase + row + (size_t)(half * 32) * HW;
        float zr[32];
        #pragma unroll
        for (int c = 0; c < 32; c++) zr[c] = zb[(size_t)c * HW];

        float bd = -1e30f; int bi = 0x7fffffff;
        #pragma unroll
        for (int k = 0; k < 4; k++) {
            int e = cs[k];
            const float4* er = reinterpret_cast<const float4*>(
                g_embn + (size_t)e * D + half * 32);
            float d0 = 0.f, d1 = 0.f, d2 = 0.f, d3 = 0.f;
            #pragma unroll
            for (int tq = 0; tq < 8; tq++) {
                float4 v = er[tq];
                d0 += zr[4 * tq + 0] * v.x;
                d1 += zr[4 * tq + 1] * v.y;
                d2 += zr[4 * tq + 2] * v.z;
                d3 += zr[4 * tq + 3] * v.w;
            }
            float part = (d0 + d1) + (d2 + d3);
            float dot = part + __shfl_xor_sync(FULL, part, 1);
            if (dot > bd || (dot == bd && e < bi)) { bd = dot; bi = e; }
        }
        if (half == 0) out[NZ + 1 + n0 + row] = (float)bi;
    }
    if (blockIdx.x == 0 && tid == 0) out[NZ] = 0.0f;
}

// ---------------------------------------------------------------------------
extern "C" void kernel_launch(void* const* d_in, const int* in_sizes, int n_in,
                              void* d_out, int out_size) {
    const float* z   = (const float*)d_in[0];
    const float* emb = (const float*)d_in[1];
    float* out = (float*)d_out;
    (void)in_sizes; (void)n_in; (void)out_size;

    prep_kernel<<<N_E / 4, 128>>>(emb);
    svq_main_kernel<<<CTAS, THREADS>>>(z, out);
}

// round 12
// speedup vs baseline: 1.3745x; 1.3745x over previous
#include <cuda_runtime.h>
#include <cuda_bf16.h>
#include <math.h>
#include <stdint.h>

// ============================================================================
// SoftVectorQuantizer via mma.sync fp16 (m16n8k16, fp32 accum), flash-style.
// z[8,64,64,64] f32, embedding[4096,64] f32.
// out = concat(z_q[2097152], entropy(=0), indices[32768] as f32)
//
// Phase-stagger build: proven 16-row/4-CTA shape (512x128, ~120 regs), with
// per-warp rotation of the pi chunk order so the 16 resident warps desync
// their LDS-heavy and HMMA-heavy phases (tensor and L1tex were both ~50%
// and serializing). fp32 ex2 restored (rel_err 4.8e-4 vs 9.9e-4).
// Algebra: unit-norm rows -> logits <= 1 -> fixed shift exp((s-1)/tau);
// final l2norm absorbs softmax denominator. argmax: fp16 top-2 + exact fp32
// refine fused into the kernel tail.
// ============================================================================

#define N_E     4096
#define D       64
#define HW      4096
#define NZ      2097152
#define NROWS   32768
#define CTAS    512          // 64 rows per CTA
#define THREADS 128          // 4 warps x 16 rows
#define NT      64           // embedding tiles of 64
#define CE      20.60992529f // log2(e)/0.07

__device__ float    g_embn[N_E * D];      // normalized embedding (refine)
__device__ uint32_t g_kf[NT * 2048];      // fp16 K B-frags (uint4-grouped), 8KB/tile
__device__ uint16_t g_vf[NT * 4096];      // fp16 V B-frags (uint4-grouped), 8KB/tile

__device__ __forceinline__ float ex2f(float x) {
    float r; asm("ex2.approx.f32 %0, %1;" : "=f"(r) : "f"(x)); return r;
}
__device__ __forceinline__ uint32_t pack_h2(float lo, float hi) {
    uint32_t r; asm("cvt.rn.f16x2.f32 %0, %1, %2;" : "=r"(r) : "f"(hi), "f"(lo));
    return r;
}
__device__ __forceinline__ uint32_t smem_u32(const void* p) {
    uint32_t a;
    asm("{ .reg .u64 t; cvta.to.shared.u64 t, %1; cvt.u32.u64 %0, t; }"
        : "=r"(a) : "l"(p));
    return a;
}
__device__ __forceinline__ void cpa16(uint32_t dst, const void* src) {
    asm volatile("cp.async.cg.shared.global [%0], [%1], 16;" :: "r"(dst), "l"(src));
}
__device__ __forceinline__ void mma_f16(float c[4], const uint32_t a[4],
                                        uint32_t b0, uint32_t b1) {
    asm volatile(
        "mma.sync.aligned.m16n8k16.row.col.f32.f16.f16.f32 "
        "{%0,%1,%2,%3},{%4,%5,%6,%7},{%8,%9},{%0,%1,%2,%3};"
        : "+f"(c[0]), "+f"(c[1]), "+f"(c[2]), "+f"(c[3])
        : "r"(a[0]), "r"(a[1]), "r"(a[2]), "r"(a[3]), "r"(b0), "r"(b1));
}

// Fragment half-index helpers (uint4-grouped layouts, 4096 halves per tile).
// GEMM1 (S = Q.K^T): n-dim = e, k-dim = d.
__device__ __forceinline__ int kf_hidx(int e, int d) {
    return ((((e >> 3) * 2 + (d >> 5)) * 32 + (e & 7) * 4 + ((d >> 1) & 3)) * 8)
           + ((d >> 4) & 1) * 4 + ((d >> 3) & 1) * 2 + (d & 1);
}
// GEMM2 (O += P.V): n-dim = d, k-dim = e.
__device__ __forceinline__ int vf_hidx(int e, int d) {
    return ((((d >> 4) * 4 + (e >> 4)) * 32 + (d & 7) * 4 + ((e >> 1) & 3)) * 8)
           + ((d >> 3) & 1) * 4 + ((e >> 3) & 1) * 2 + (e & 1);
}

// ---------------------------------------------------------------------------
// prep: normalize embedding rows + scatter fp16 B-fragments (once)
// ---------------------------------------------------------------------------
__global__ void prep_kernel(const float* __restrict__ emb) {
    int e = blockIdx.x * 4 + (threadIdx.x >> 5);
    int lane = threadIdx.x & 31;
    float2 v = reinterpret_cast<const float2*>(emb + (size_t)e * D)[lane];
    float s = v.x * v.x + v.y * v.y;
    #pragma unroll
    for (int o = 16; o; o >>= 1) s += __shfl_xor_sync(0xffffffffu, s, o);
    float inv = 1.0f / fmaxf(sqrtf(s), 1e-12f);
    float2 r; r.x = v.x * inv; r.y = v.y * inv;
    reinterpret_cast<float2*>(g_embn + (size_t)e * D)[lane] = r;

    int tile = e >> 6, el = e & 63;
    int d0 = 2 * lane, d1 = 2 * lane + 1;
    __half h0 = __float2half_rn(r.x), h1 = __float2half_rn(r.y);
    uint16_t u0 = *reinterpret_cast<uint16_t*>(&h0);
    uint16_t u1 = *reinterpret_cast<uint16_t*>(&h1);
    g_kf[tile * 2048 + (kf_hidx(el, d0) >> 1)] = (uint32_t)u0 | ((uint32_t)u1 << 16);
    g_vf[tile * 4096 + vf_hidx(el, d0)] = u0;
    g_vf[tile * 4096 + vf_hidx(el, d1)] = u1;
}

// ---------------------------------------------------------------------------
// main fused kernel
// ---------------------------------------------------------------------------
__global__ void __launch_bounds__(THREADS, 4)
svq_main_kernel(const float* __restrict__ z, float* __restrict__ out) {
    __shared__ uint4 s_kf[2][512];   // 16 KB
    __shared__ uint4 s_vf[2][512];   // 16 KB
    __shared__ int   s_cand[64][2];  // argmax candidates

    const int tid  = threadIdx.x;
    const int w    = tid >> 5;
    const int lane = tid & 31;
    const int q    = lane & 3;
    const int r    = lane >> 2;
    const unsigned FULL = 0xffffffffu;

    const uint32_t kf_s[2] = {smem_u32(&s_kf[0][0]), smem_u32(&s_kf[1][0])};
    const uint32_t vf_s[2] = {smem_u32(&s_vf[0][0]), smem_u32(&s_vf[1][0])};

    // ---- kick off async copies of tiles 0 and 1 (8KB K + 8KB V each) ----
    #pragma unroll
    for (int tb = 0; tb < 2; tb++) {
        const char* gk = (const char*)g_kf + (size_t)tb * 8192;
        const char* gv = (const char*)g_vf + (size_t)tb * 8192;
        #pragma unroll
        for (int i = 0; i < 4; i++) {
            cpa16(kf_s[tb] + (i * 128 + tid) * 16, gk + (i * 128 + tid) * 16);
            cpa16(vf_s[tb] + (i * 128 + tid) * 16, gv + (i * 128 + tid) * 16);
        }
        asm volatile("cp.async.commit_group;");
    }

    // ---- Q: 16 rows/warp, l2-normalize, fp16 A-frags (overlaps copies) ----
    const int n0  = blockIdx.x * 64;          // first row of this CTA
    const int bb  = n0 >> 12;
    const int hw0 = n0 & (HW - 1);
    const float* zbase = z + (size_t)bb * D * HW + hw0;
    const int wrow = w * 16;                  // warp's first row (CTA-local)

    uint32_t qa[4][4];
    {
        float zq[4][4][2];
        float ssq[2] = {0.f, 0.f};
        #pragma unroll
        for (int ks = 0; ks < 4; ks++)
            #pragma unroll
            for (int a = 0; a < 4; a++) {
                int row = wrow + r + (a & 1) * 8;
                int k   = ks * 16 + 2 * q + ((a & 2) ? 8 : 0);
                float v0 = zbase[(size_t)k * HW + row];
                float v1 = zbase[(size_t)(k + 1) * HW + row];
                zq[ks][a][0] = v0;
                zq[ks][a][1] = v1;
                ssq[a & 1] += v0 * v0 + v1 * v1;
            }
        #pragma unroll
        for (int s = 0; s < 2; s++) {
            ssq[s] += __shfl_xor_sync(FULL, ssq[s], 1);
            ssq[s] += __shfl_xor_sync(FULL, ssq[s], 2);
            ssq[s] = 1.0f / fmaxf(sqrtf(ssq[s]), 1e-12f);
        }
        #pragma unroll
        for (int ks = 0; ks < 4; ks++)
            #pragma unroll
            for (int a = 0; a < 4; a++) {
                float sc = ssq[a & 1];
                qa[ks][a] = pack_h2(zq[ks][a][0] * sc, zq[ks][a][1] * sc);
            }
    }

    float o[8][4];
    #pragma unroll
    for (int di = 0; di < 8; di++)
        #pragma unroll
        for (int c = 0; c < 4; c++) o[di][c] = 0.f;
    float m1[2] = {-1e30f, -1e30f}, m2[2] = {-1e30f, -1e30f};
    int   i1[2] = {0, 0}, i2[2] = {0, 0};

    for (int t = 0; t < NT; t++) {
        const int cur = t & 1;
        if (t + 1 < NT) asm volatile("cp.async.wait_group 1;");
        else            asm volatile("cp.async.wait_group 0;");
        __syncthreads();

        const uint4* ks4 = s_kf[cur];
        const uint4* vs4 = s_vf[cur];

        #pragma unroll
        for (int pp = 0; pp < 4; pp++) {
            const int pi = (pp + w) & 3;   // per-warp phase stagger

            // GEMM1: two n8 chunks (16 embeddings), uint4 loads (2 k-steps each)
            float s[2][4];
            #pragma unroll
            for (int nih = 0; nih < 2; nih++)
                #pragma unroll
                for (int c = 0; c < 4; c++) s[nih][c] = 0.f;
            #pragma unroll
            for (int nih = 0; nih < 2; nih++) {
                const int ni = pi * 2 + nih;
                #pragma unroll
                for (int kp = 0; kp < 2; kp++) {
                    uint4 bk = ks4[(ni * 2 + kp) * 32 + lane];
                    mma_f16(s[nih], qa[2 * kp],     bk.x, bk.y);
                    mma_f16(s[nih], qa[2 * kp + 1], bk.z, bk.w);
                }
            }
            // exp (fp32 MUFU for precision) -> fp16 A-frags
            uint32_t a[4];
            #pragma unroll
            for (int nih = 0; nih < 2; nih++) {
                float p0 = ex2f(fmaf(s[nih][0], CE, -CE));
                float p1 = ex2f(fmaf(s[nih][1], CE, -CE));
                float p2 = ex2f(fmaf(s[nih][2], CE, -CE));
                float p3 = ex2f(fmaf(s[nih][3], CE, -CE));
                a[nih * 2 + 0] = pack_h2(p0, p1);
                a[nih * 2 + 1] = pack_h2(p2, p3);
            }
            // GEMM2: O += P(k16) * V, uint4 loads (2 n-chunks each)
            #pragma unroll
            for (int dp = 0; dp < 4; dp++) {
                uint4 bv = vs4[(dp * 4 + pi) * 32 + lane];
                mma_f16(o[2 * dp],     a, bv.x, bv.y);
                mma_f16(o[2 * dp + 1], a, bv.z, bv.w);
            }
            // top-2 tracking, gated by pair-max
            #pragma unroll
            for (int nih = 0; nih < 2; nih++)
                #pragma unroll
                for (int slot = 0; slot < 2; slot++) {
                    float s0 = s[nih][slot * 2], s1 = s[nih][slot * 2 + 1];
                    if (fmaxf(s0, s1) > m2[slot]) {
                        int col0 = t * 64 + (pi * 2 + nih) * 8 + 2 * q;
                        if (s0 > m2[slot]) {
                            if (s0 > m1[slot]) {
                                m2[slot] = m1[slot]; i2[slot] = i1[slot];
                                m1[slot] = s0;       i1[slot] = col0;
                            } else { m2[slot] = s0; i2[slot] = col0; }
                        }
                        if (s1 > m2[slot]) {
                            if (s1 > m1[slot]) {
                                m2[slot] = m1[slot]; i2[slot] = i1[slot];
                                m1[slot] = s1;       i1[slot] = col0 + 1;
                            } else { m2[slot] = s1; i2[slot] = col0 + 1; }
                        }
                    }
                }
        }
        __syncthreads();

        // issue copy of tile t+2 into the freed buffer
        if (t + 2 < NT) {
            const char* gk = (const char*)g_kf + (size_t)(t + 2) * 8192;
            const char* gv = (const char*)g_vf + (size_t)(t + 2) * 8192;
            #pragma unroll
            for (int i = 0; i < 4; i++) {
                cpa16(kf_s[cur] + (i * 128 + tid) * 16, gk + (i * 128 + tid) * 16);
                cpa16(vf_s[cur] + (i * 128 + tid) * 16, gv + (i * 128 + tid) * 16);
            }
            asm volatile("cp.async.commit_group;");
        }
    }

    // ---- O: per-row l2norm + store ----
    {
        float oss[2] = {0.f, 0.f};
        #pragma unroll
        for (int di = 0; di < 8; di++) {
            oss[0] += o[di][0] * o[di][0] + o[di][1] * o[di][1];
            oss[1] += o[di][2] * o[di][2] + o[di][3] * o[di][3];
        }
        #pragma unroll
        for (int s = 0; s < 2; s++) {
            oss[s] += __shfl_xor_sync(FULL, oss[s], 1);
            oss[s] += __shfl_xor_sync(FULL, oss[s], 2);
            oss[s] = 1.0f / fmaxf(sqrtf(oss[s]), 1e-12f);
        }
        float* ob = out + (size_t)bb * D * HW + hw0;
        #pragma unroll
        for (int di = 0; di < 8; di++) {
            int d0 = di * 8 + 2 * q;
            int rl = wrow + r, rh = rl + 8;
            ob[(size_t)d0 * HW + rl]       = o[di][0] * oss[0];
            ob[(size_t)(d0 + 1) * HW + rl] = o[di][1] * oss[0];
            ob[(size_t)d0 * HW + rh]       = o[di][2] * oss[1];
            ob[(size_t)(d0 + 1) * HW + rh] = o[di][3] * oss[1];
        }
    }

    // ---- merge top-2 across the 4 quad lanes of each row ----
    #pragma unroll
    for (int s = 0; s < 2; s++) {
        #pragma unroll
        for (int off = 1; off <= 2; off++) {
            float om1 = __shfl_xor_sync(FULL, m1[s], off);
            int   oi1 = __shfl_xor_sync(FULL, i1[s], off);
            float om2 = __shfl_xor_sync(FULL, m2[s], off);
            int   oi2 = __shfl_xor_sync(FULL, i2[s], off);
            if (om1 > m1[s] || (om1 == m1[s] && oi1 < i1[s])) {
                float tm = m1[s]; int ti = i1[s];
                m1[s] = om1; i1[s] = oi1;
                om1 = tm; oi1 = ti;
            }
            if (om1 > m2[s] || (om1 == m2[s] && oi1 < i2[s])) { m2[s] = om1; i2[s] = oi1; }
            if (om2 > m2[s] || (om2 == m2[s] && oi2 < i2[s])) { m2[s] = om2; i2[s] = oi2; }
        }
    }
    if (q == 0) {
        s_cand[wrow + r][0]     = i1[0];
        s_cand[wrow + r][1]     = i2[0];
        s_cand[wrow + r + 8][0] = i1[1];
        s_cand[wrow + r + 8][1] = i2[1];
    }
    __syncthreads();

    // ---- fused exact-fp32 argmax refine: 2 threads per row ----
    {
        const int row  = tid >> 1;       // CTA-local row 0..63
        const int half = tid & 1;        // channel half
        const int c1 = s_cand[row][0], c2 = s_cand[row][1];
        const float* zb = zbase + row + (size_t)(half * 32) * HW;
        float zr[32];
        #pragma unroll
        for (int c = 0; c < 32; c++) zr[c] = zb[(size_t)c * HW];

        float bd = -1e30f; int bi = 0x7fffffff;
        #pragma unroll
        for (int k = 0; k < 2; k++) {
            int e = (k == 0) ? c1 : c2;
            const float4* er = reinterpret_cast<const float4*>(
                g_embn + (size_t)e * D + half * 32);
            float d0 = 0.f, d1 = 0.f, d2 = 0.f, d3 = 0.f;
            #pragma unroll
            for (int tq = 0; tq < 8; tq++) {
                float4 v = er[tq];
                d0 += zr[4 * tq + 0] * v.x;
                d1 += zr[4 * tq + 1] * v.y;
                d2 += zr[4 * tq + 2] * v.z;
                d3 += zr[4 * tq + 3] * v.w;
            }
            float part = (d0 + d1) + (d2 + d3);
            float dot = part + __shfl_xor_sync(FULL, part, 1);
            if (dot > bd || (dot == bd && e < bi)) { bd = dot; bi = e; }
        }
        if (half == 0) out[NZ + 1 + n0 + row] = (float)bi;
    }
    if (blockIdx.x == 0 && tid == 0) out[NZ] = 0.0f;
}

// ---------------------------------------------------------------------------
extern "C" void kernel_launch(void* const* d_in, const int* in_sizes, int n_in,
                              void* d_out, int out_size) {
    const float* z   = (const float*)d_in[0];
    const float* emb = (const float*)d_in[1];
    float* out = (float*)d_out;
    (void)in_sizes; (void)n_in; (void)out_size;

    prep_kernel<<<N_E / 4, 128>>>(emb);
    svq_main_kernel<<<CTAS, THREADS>>>(z, out);
}

// round 13
// speedup vs baseline: 1.4999x; 1.0912x over previous
#include <cuda_runtime.h>
#include <cuda_bf16.h>
#include <math.h>
#include <stdint.h>

// ============================================================================
// SoftVectorQuantizer via mma.sync fp16 (m16n8k16, fp32 accum), flash-style.
// z[8,64,64,64] f32, embedding[4096,64] f32.
// out = concat(z_q[2097152], entropy(=0), indices[32768] as f32)
//
// Combined-best build (from 12-round ablation):
//  - movmatrix: GEMM2's V B-frags derived in-register from GEMM1's K B-frags
//    (V never in smem -> half cp.async, 17KB smem)            [R8: -4.3us]
//  - ex2.approx.f16x2 for exp (half MUFU + half CVT)          [R6: -10us]
//  - softmax shift m=0.6 instead of 1.0: any per-row-uniform shift cancels
//    in the final l2norm; m=0.6 shrinks mass-bearing |t| ~5x -> fp16
//    argument quantization error drops from ~8.6e-4 to ~2.5e-4, and
//    p <= e^(0.4/0.07) ~= 302 can never overflow fp16 (s <= 1 always).
// Shape: 512 CTAs x 128 thr, 16 rows/warp, 4 CTAs/SM (the only shape that
// reaches ~132us; M=32 and e-split variants all regressed).
// argmax: fp16 top-2 + exact fp32 refine fused into the kernel tail.
// ============================================================================

#define N_E     4096
#define D       64
#define HW      4096
#define NZ      2097152
#define NROWS   32768
#define CTAS    512          // 64 rows per CTA
#define THREADS 128          // 4 warps x 16 rows
#define NT      64           // embedding tiles of 64
#define CE      20.60992529f // log2(e)/0.07
#define CM      12.36595517f // 0.6 * CE  (softmax shift m = 0.6)

__device__ float    g_embn[N_E * D];      // normalized embedding (refine)
__device__ uint32_t g_kf[NT * 2048];      // fp16 K B-frags (uint4-grouped), 8KB/tile

__device__ __forceinline__ uint32_t ex2_h2(uint32_t h) {
    uint32_t r; asm("ex2.approx.f16x2 %0, %1;" : "=r"(r) : "r"(h)); return r;
}
__device__ __forceinline__ uint32_t pack_h2(float lo, float hi) {
    uint32_t r; asm("cvt.rn.f16x2.f32 %0, %1, %2;" : "=r"(r) : "f"(hi), "f"(lo));
    return r;
}
__device__ __forceinline__ uint32_t movm_t(uint32_t s) {
    uint32_t d;
    asm("movmatrix.sync.aligned.m8n8.trans.b16 %0, %1;" : "=r"(d) : "r"(s));
    return d;
}
__device__ __forceinline__ uint32_t smem_u32(const void* p) {
    uint32_t a;
    asm("{ .reg .u64 t; cvta.to.shared.u64 t, %1; cvt.u32.u64 %0, t; }"
        : "=r"(a) : "l"(p));
    return a;
}
__device__ __forceinline__ void cpa16(uint32_t dst, const void* src) {
    asm volatile("cp.async.cg.shared.global [%0], [%1], 16;" :: "r"(dst), "l"(src));
}
__device__ __forceinline__ void mma_f16(float c[4], const uint32_t a[4],
                                        uint32_t b0, uint32_t b1) {
    asm volatile(
        "mma.sync.aligned.m16n8k16.row.col.f32.f16.f16.f32 "
        "{%0,%1,%2,%3},{%4,%5,%6,%7},{%8,%9},{%0,%1,%2,%3};"
        : "+f"(c[0]), "+f"(c[1]), "+f"(c[2]), "+f"(c[3])
        : "r"(a[0]), "r"(a[1]), "r"(a[2]), "r"(a[3]), "r"(b0), "r"(b1));
}

// K-frag half-index (uint4-grouped, 4096 halves per 64x64 tile).
// uint4 at [(ni*2+kp)*32 + lane] holds b-regs (ni, j=4kp..4kp+3):
// each b-reg (ni,j) = canonical 8x8 frag of emb[e in 8ni..][d in 8j..].
__device__ __forceinline__ int kf_hidx(int e, int d) {
    return ((((e >> 3) * 2 + (d >> 5)) * 32 + (e & 7) * 4 + ((d >> 1) & 3)) * 8)
           + ((d >> 4) & 1) * 4 + ((d >> 3) & 1) * 2 + (d & 1);
}

// ---------------------------------------------------------------------------
// prep: normalize embedding rows + scatter fp16 K B-fragments (once)
// ---------------------------------------------------------------------------
__global__ void prep_kernel(const float* __restrict__ emb) {
    int e = blockIdx.x * 4 + (threadIdx.x >> 5);
    int lane = threadIdx.x & 31;
    float2 v = reinterpret_cast<const float2*>(emb + (size_t)e * D)[lane];
    float s = v.x * v.x + v.y * v.y;
    #pragma unroll
    for (int o = 16; o; o >>= 1) s += __shfl_xor_sync(0xffffffffu, s, o);
    float inv = 1.0f / fmaxf(sqrtf(s), 1e-12f);
    float2 r; r.x = v.x * inv; r.y = v.y * inv;
    reinterpret_cast<float2*>(g_embn + (size_t)e * D)[lane] = r;

    int tile = e >> 6, el = e & 63;
    __half h0 = __float2half_rn(r.x), h1 = __float2half_rn(r.y);
    uint16_t u0 = *reinterpret_cast<uint16_t*>(&h0);
    uint16_t u1 = *reinterpret_cast<uint16_t*>(&h1);
    g_kf[tile * 2048 + (kf_hidx(el, 2 * lane) >> 1)] =
        (uint32_t)u0 | ((uint32_t)u1 << 16);
}

// ---------------------------------------------------------------------------
// main fused kernel
// ---------------------------------------------------------------------------
__global__ void __launch_bounds__(THREADS, 4)
svq_main_kernel(const float* __restrict__ z, float* __restrict__ out) {
    __shared__ uint4 s_kf[2][512];   // 16 KB (double-buffered K tiles)
    __shared__ int   s_cand[64][2];  // argmax candidates

    const int tid  = threadIdx.x;
    const int w    = tid >> 5;
    const int lane = tid & 31;
    const int q    = lane & 3;
    const int r    = lane >> 2;
    const unsigned FULL = 0xffffffffu;

    const uint32_t kf_s[2] = {smem_u32(&s_kf[0][0]), smem_u32(&s_kf[1][0])};

    // ---- kick off async copies of K tiles 0 and 1 (8KB each) ----
    #pragma unroll
    for (int tb = 0; tb < 2; tb++) {
        const char* gk = (const char*)g_kf + (size_t)tb * 8192;
        #pragma unroll
        for (int i = 0; i < 4; i++)
            cpa16(kf_s[tb] + (i * 128 + tid) * 16, gk + (i * 128 + tid) * 16);
        asm volatile("cp.async.commit_group;");
    }

    // ---- Q: 16 rows/warp, l2-normalize, fp16 A-frags (overlaps copies) ----
    const int n0  = blockIdx.x * 64;          // first row of this CTA
    const int bb  = n0 >> 12;
    const int hw0 = n0 & (HW - 1);
    const float* zbase = z + (size_t)bb * D * HW + hw0;
    const int wrow = w * 16;                  // warp's first row (CTA-local)

    uint32_t qa[4][4];
    {
        float zq[4][4][2];
        float ssq[2] = {0.f, 0.f};
        #pragma unroll
        for (int ks = 0; ks < 4; ks++)
            #pragma unroll
            for (int a = 0; a < 4; a++) {
                int row = wrow + r + (a & 1) * 8;
                int k   = ks * 16 + 2 * q + ((a & 2) ? 8 : 0);
                float v0 = zbase[(size_t)k * HW + row];
                float v1 = zbase[(size_t)(k + 1) * HW + row];
                zq[ks][a][0] = v0;
                zq[ks][a][1] = v1;
                ssq[a & 1] += v0 * v0 + v1 * v1;
            }
        #pragma unroll
        for (int s = 0; s < 2; s++) {
            ssq[s] += __shfl_xor_sync(FULL, ssq[s], 1);
            ssq[s] += __shfl_xor_sync(FULL, ssq[s], 2);
            ssq[s] = 1.0f / fmaxf(sqrtf(ssq[s]), 1e-12f);
        }
        #pragma unroll
        for (int ks = 0; ks < 4; ks++)
            #pragma unroll
            for (int a = 0; a < 4; a++) {
                float sc = ssq[a & 1];
                qa[ks][a] = pack_h2(zq[ks][a][0] * sc, zq[ks][a][1] * sc);
            }
    }

    float o[8][4];
    #pragma unroll
    for (int di = 0; di < 8; di++)
        #pragma unroll
        for (int c = 0; c < 4; c++) o[di][c] = 0.f;
    float m1[2] = {-1e30f, -1e30f}, m2[2] = {-1e30f, -1e30f};
    int   i1[2] = {0, 0}, i2[2] = {0, 0};

    for (int t = 0; t < NT; t++) {
        const int cur = t & 1;
        if (t + 1 < NT) asm volatile("cp.async.wait_group 1;");
        else            asm volatile("cp.async.wait_group 0;");
        __syncthreads();

        const uint4* ks4 = s_kf[cur];

        #pragma unroll
        for (int pi = 0; pi < 4; pi++) {
            // load K b-regs for e in [16pi, 16pi+16): bk[nih][kp]
            uint4 bk[2][2];
            #pragma unroll
            for (int nih = 0; nih < 2; nih++)
                #pragma unroll
                for (int kp = 0; kp < 2; kp++)
                    bk[nih][kp] = ks4[((pi * 2 + nih) * 2 + kp) * 32 + lane];

            // GEMM1: S chunks (16 embeddings)
            float s[2][4];
            #pragma unroll
            for (int nih = 0; nih < 2; nih++) {
                #pragma unroll
                for (int c = 0; c < 4; c++) s[nih][c] = 0.f;
                mma_f16(s[nih], qa[0], bk[nih][0].x, bk[nih][0].y);
                mma_f16(s[nih], qa[1], bk[nih][0].z, bk[nih][0].w);
                mma_f16(s[nih], qa[2], bk[nih][1].x, bk[nih][1].y);
                mma_f16(s[nih], qa[3], bk[nih][1].z, bk[nih][1].w);
            }
            // exp: fp32 fma -> f16x2 pack -> one MUFU per pair.
            // Shift m=0.6 keeps fp16 argument small where softmax mass lives
            // AND cannot overflow (s<=1 -> p <= e^(0.4/0.07) ~= 302).
            uint32_t a[4];
            #pragma unroll
            for (int nih = 0; nih < 2; nih++) {
                float t0 = fmaf(s[nih][0], CE, -CM);
                float t1 = fmaf(s[nih][1], CE, -CM);
                float t2 = fmaf(s[nih][2], CE, -CM);
                float t3 = fmaf(s[nih][3], CE, -CM);
                a[nih * 2 + 0] = ex2_h2(pack_h2(t0, t1));
                a[nih * 2 + 1] = ex2_h2(pack_h2(t2, t3));
            }
            // GEMM2: O += P(k16=e) * V; V b-regs = movmatrix of K b-regs
            #pragma unroll
            for (int di = 0; di < 8; di++) {
                uint32_t kb0 = (di < 4)
                    ? ((di & 2) ? ((di & 1) ? bk[0][0].w : bk[0][0].z)
                                : ((di & 1) ? bk[0][0].y : bk[0][0].x))
                    : ((di & 2) ? ((di & 1) ? bk[0][1].w : bk[0][1].z)
                                : ((di & 1) ? bk[0][1].y : bk[0][1].x));
                uint32_t kb1 = (di < 4)
                    ? ((di & 2) ? ((di & 1) ? bk[1][0].w : bk[1][0].z)
                                : ((di & 1) ? bk[1][0].y : bk[1][0].x))
                    : ((di & 2) ? ((di & 1) ? bk[1][1].w : bk[1][1].z)
                                : ((di & 1) ? bk[1][1].y : bk[1][1].x));
                mma_f16(o[di], a, movm_t(kb0), movm_t(kb1));
            }
            // top-2 tracking, gated by pair-max
            #pragma unroll
            for (int nih = 0; nih < 2; nih++)
                #pragma unroll
                for (int slot = 0; slot < 2; slot++) {
                    float s0 = s[nih][slot * 2], s1 = s[nih][slot * 2 + 1];
                    if (fmaxf(s0, s1) > m2[slot]) {
                        int col0 = t * 64 + (pi * 2 + nih) * 8 + 2 * q;
                        if (s0 > m2[slot]) {
                            if (s0 > m1[slot]) {
                                m2[slot] = m1[slot]; i2[slot] = i1[slot];
                                m1[slot] = s0;       i1[slot] = col0;
                            } else { m2[slot] = s0; i2[slot] = col0; }
                        }
                        if (s1 > m2[slot]) {
                            if (s1 > m1[slot]) {
                                m2[slot] = m1[slot]; i2[slot] = i1[slot];
                                m1[slot] = s1;       i1[slot] = col0 + 1;
                            } else { m2[slot] = s1; i2[slot] = col0 + 1; }
                        }
                    }
                }
        }
        __syncthreads();

        // issue copy of tile t+2 into the freed buffer
        if (t + 2 < NT) {
            const char* gk = (const char*)g_kf + (size_t)(t + 2) * 8192;
            #pragma unroll
            for (int i = 0; i < 4; i++)
                cpa16(kf_s[cur] + (i * 128 + tid) * 16, gk + (i * 128 + tid) * 16);
            asm volatile("cp.async.commit_group;");
        }
    }

    // ---- O: per-row l2norm + store ----
    {
        float oss[2] = {0.f, 0.f};
        #pragma unroll
        for (int di = 0; di < 8; di++) {
            oss[0] += o[di][0] * o[di][0] + o[di][1] * o[di][1];
            oss[1] += o[di][2] * o[di][2] + o[di][3] * o[di][3];
        }
        #pragma unroll
        for (int s = 0; s < 2; s++) {
            oss[s] += __shfl_xor_sync(FULL, oss[s], 1);
            oss[s] += __shfl_xor_sync(FULL, oss[s], 2);
            oss[s] = 1.0f / fmaxf(sqrtf(oss[s]), 1e-12f);
        }
        float* ob = out + (size_t)bb * D * HW + hw0;
        #pragma unroll
        for (int di = 0; di < 8; di++) {
            int d0 = di * 8 + 2 * q;
            int rl = wrow + r, rh = rl + 8;
            ob[(size_t)d0 * HW + rl]       = o[di][0] * oss[0];
            ob[(size_t)(d0 + 1) * HW + rl] = o[di][1] * oss[0];
            ob[(size_t)d0 * HW + rh]       = o[di][2] * oss[1];
            ob[(size_t)(d0 + 1) * HW + rh] = o[di][3] * oss[1];
        }
    }

    // ---- merge top-2 across the 4 quad lanes of each row ----
    #pragma unroll
    for (int s = 0; s < 2; s++) {
        #pragma unroll
        for (int off = 1; off <= 2; off++) {
            float om1 = __shfl_xor_sync(FULL, m1[s], off);
            int   oi1 = __shfl_xor_sync(FULL, i1[s], off);
            float om2 = __shfl_xor_sync(FULL, m2[s], off);
            int   oi2 = __shfl_xor_sync(FULL, i2[s], off);
            if (om1 > m1[s] || (om1 == m1[s] && oi1 < i1[s])) {
                float tm = m1[s]; int ti = i1[s];
                m1[s] = om1; i1[s] = oi1;
                om1 = tm; oi1 = ti;
            }
            if (om1 > m2[s] || (om1 == m2[s] && oi1 < i2[s])) { m2[s] = om1; i2[s] = oi1; }
            if (om2 > m2[s] || (om2 == m2[s] && oi2 < i2[s])) { m2[s] = om2; i2[s] = oi2; }
        }
    }
    if (q == 0) {
        s_cand[wrow + r][0]     = i1[0];
        s_cand[wrow + r][1]     = i2[0];
        s_cand[wrow + r + 8][0] = i1[1];
        s_cand[wrow + r + 8][1] = i2[1];
    }
    __syncthreads();

    // ---- fused exact-fp32 argmax refine: 2 threads per row ----
    {
        const int row  = tid >> 1;       // CTA-local row 0..63
        const int half = tid & 1;        // channel half
        const int c1 = s_cand[row][0], c2 = s_cand[row][1];
        const float* zb = zbase + row + (size_t)(half * 32) * HW;
        float zr[32];
        #pragma unroll
        for (int c = 0; c < 32; c++) zr[c] = zb[(size_t)c * HW];

        float bd = -1e30f; int bi = 0x7fffffff;
        #pragma unroll
        for (int k = 0; k < 2; k++) {
            int e = (k == 0) ? c1 : c2;
            const float4* er = reinterpret_cast<const float4*>(
                g_embn + (size_t)e * D + half * 32);
            float d0 = 0.f, d1 = 0.f, d2 = 0.f, d3 = 0.f;
            #pragma unroll
            for (int tq = 0; tq < 8; tq++) {
                float4 v = er[tq];
                d0 += zr[4 * tq + 0] * v.x;
                d1 += zr[4 * tq + 1] * v.y;
                d2 += zr[4 * tq + 2] * v.z;
                d3 += zr[4 * tq + 3] * v.w;
            }
            float part = (d0 + d1) + (d2 + d3);
            float dot = part + __shfl_xor_sync(FULL, part, 1);
            if (dot > bd || (dot == bd && e < bi)) { bd = dot; bi = e; }
        }
        if (half == 0) out[NZ + 1 + n0 + row] = (float)bi;
    }
    if (blockIdx.x == 0 && tid == 0) out[NZ] = 0.0f;
}

// ---------------------------------------------------------------------------
extern "C" void kernel_launch(void* const* d_in, const int* in_sizes, int n_in,
                              void* d_out, int out_size) {
    const float* z   = (const float*)d_in[0];
    const float* emb = (const float*)d_in[1];
    float* out = (float*)d_out;
    (void)in_sizes; (void)n_in; (void)out_size;

    prep_kernel<<<N_E / 4, 128>>>(emb);
    svq_main_kernel<<<CTAS, THREADS>>>(z, out);
}